// round 6
// baseline (speedup 1.0000x reference)
#include <cuda_runtime.h>
#include <cstdint>

// Problem constants
#define Bn 4
#define Cn 32
#define Ln 256
#define Mn 256
#define Fn 8
#define Nn 64
#define FC (Fn * Cn)          // 256
#define LM (Ln * Mn)          // 65536
#define IMAG_OFF ((size_t)Bn * Fn * LM)  // 2,097,152

#define TL 4                  // l per block
#define THREADS 512           // 16 warps
#define STAGES 8
#define STAGE_BYTES (2 * TL * Mn * 4)     // 8192 (xr 4KB + xi 4KB)
#define SX_BYTES (STAGES * STAGE_BYTES)   // 65536
#define SW_BYTES (TL * FC * 16)           // 16384
#define SMEM_TOTAL (SX_BYTES + SW_BYTES + 256)

union U64 {
    unsigned long long u;
    float2 f;
};

__device__ __forceinline__ unsigned long long ffma2(unsigned long long a,
                                                    unsigned long long b,
                                                    unsigned long long c) {
    unsigned long long d;
    asm("fma.rn.f32x2 %0, %1, %2, %3;" : "=l"(d) : "l"(a), "l"(b), "l"(c));
    return d;
}

__device__ __forceinline__ uint32_t smem_u32(const void* p) {
    uint32_t a;
    asm("{ .reg .u64 t; cvta.to.shared.u64 t, %1; cvt.u32.u64 %0, t; }"
        : "=r"(a) : "l"(p));
    return a;
}

__device__ __forceinline__ void bulk_cp(uint32_t sdst, const void* gsrc,
                                        uint32_t bytes, uint32_t bar) {
    asm volatile(
        "cp.async.bulk.shared::cta.global.mbarrier::complete_tx::bytes "
        "[%0], [%1], %2, [%3];"
        :: "r"(sdst), "l"(gsrc), "r"(bytes), "r"(bar) : "memory");
}

__device__ __forceinline__ void mbar_init(uint32_t bar, uint32_t count) {
    asm volatile("mbarrier.init.shared.b64 [%0], %1;" :: "r"(bar), "r"(count)
                 : "memory");
}

__device__ __forceinline__ void mbar_expect_tx(uint32_t bar, uint32_t bytes) {
    asm volatile("mbarrier.arrive.expect_tx.shared.b64 _, [%0], %1;"
                 :: "r"(bar), "r"(bytes) : "memory");
}

__device__ __forceinline__ void mbar_arrive(uint32_t bar) {
    asm volatile("mbarrier.arrive.release.cta.shared::cta.b64 _, [%0];"
                 :: "r"(bar) : "memory");
}

__device__ __forceinline__ void mbar_wait(uint32_t bar, uint32_t parity) {
    asm volatile(
        "{\n\t"
        ".reg .pred P;\n\t"
        "WAIT_%=:\n\t"
        "mbarrier.try_wait.parity.acquire.cta.shared::cta.b64 P, [%0], %1, 0x989680;\n\t"
        "@P bra DONE_%=;\n\t"
        "bra WAIT_%=;\n\t"
        "DONE_%=:\n\t"
        "}"
        :: "r"(bar), "r"(parity) : "memory");
}

__device__ __forceinline__ void fence_async() {
    asm volatile("fence.proxy.async.shared::cta;" ::: "memory");
}

// ---------------------------------------------------------------------------
// Grid: B * (L/TL) = 256 blocks, 512 threads.
// Block handles (b, lt..lt+3). Chunk = one c: 4KB xr + 4KB xi (contiguous!).
// 8-stage ring, producer tid0, consumers arrive on empty barriers per warp.
// Thread t: l-sub = t>>7, m-pair = t&127, all 8 f.
// ---------------------------------------------------------------------------
__global__ __launch_bounds__(THREADS, 2) void sphere_tl_kernel(
    const float* __restrict__ xr,
    const float* __restrict__ xi,
    const float* __restrict__ wr,
    const float* __restrict__ wi,
    float* __restrict__ out) {
    extern __shared__ __align__(16) char smem[];
    float* sx = reinterpret_cast<float*>(smem);                   // ring
    ulonglong2* sw = reinterpret_cast<ulonglong2*>(smem + SX_BYTES); // [TL][FC]
    uint32_t full0 = smem_u32(smem + SX_BYTES + SW_BYTES);
    uint32_t empty0 = full0 + STAGES * 8;

    int bid = blockIdx.x;
    int b = bid >> 6;                  // / (Ln/TL)
    int lt = (bid & 63) * TL;
    int tid = threadIdx.x;

    // --- interpolate weights for l = lt..lt+3 into sw[li][f*Cn+c] ---
#pragma unroll
    for (int j = 0; j < 2; ++j) {
        int k = tid + j * THREADS;     // [0, 1024)
        int li = k >> 8;
        int idx = k & 255;             // f*Cn + c
        int l = lt + li;
        float t = (float)l * (63.0f / 255.0f);
        int lo = (int)t;
        if (lo > Nn - 2) lo = Nn - 2;
        float fr = t - (float)lo;
        float om = 1.0f - fr;
        const float* pwr = wr + idx * Nn + lo;
        const float* pwi = wi + idx * Nn + lo;
        float vr = pwr[0] * om + pwr[1] * fr;
        float vi = pwi[0] * om + pwi[1] * fr;
        U64 ur, ui;
        ur.f = make_float2(vr, vr);
        ui.f = make_float2(vi, vi);
        sw[li * FC + idx] = make_ulonglong2(ur.u, ui.u);
    }

    if (tid == 0) {
#pragma unroll
        for (int s = 0; s < STAGES; ++s) {
            mbar_init(full0 + s * 8, 1);
            mbar_init(empty0 + s * 8, 16);   // one arrive per warp
        }
        fence_async();
    }
    __syncthreads();

    const char* gxr = reinterpret_cast<const char*>(
        xr + ((size_t)b * Cn * Ln + lt) * Mn);
    const char* gxi = reinterpret_cast<const char*>(
        xi + ((size_t)b * Cn * Ln + lt) * Mn);
    uint32_t sxb = smem_u32(sx);
    const size_t cstride = (size_t)Ln * Mn * 4;   // bytes per c

    // prologue: fill all 8 stages (chunks 0..7), 4KB copies
    if (tid == 0) {
#pragma unroll
        for (int k = 0; k < STAGES; ++k) {
            uint32_t bar = full0 + k * 8;
            uint32_t sdst = sxb + k * STAGE_BYTES;
            mbar_expect_tx(bar, STAGE_BYTES);
            bulk_cp(sdst, gxr + (size_t)k * cstride, TL * Mn * 4, bar);
            bulk_cp(sdst + TL * Mn * 4, gxi + (size_t)k * cstride, TL * Mn * 4, bar);
        }
    }

    int li = tid >> 7;
    int mt = tid & 127;
    int lane = tid & 31;
    const ulonglong2* swl = sw + li * FC;

    unsigned long long ar[8], ai[8];
#pragma unroll
    for (int f = 0; f < 8; ++f) { ar[f] = 0ull; ai[f] = 0ull; }

    const unsigned long long SMSK = 0x8000000080000000ULL;
    const unsigned long long* sxu =
        reinterpret_cast<const unsigned long long*>(sx);
    int xoff = li * (Mn / 2) + mt;     // u64 index within a 4KB half-stage

    for (int c = 0; c < Cn; ++c) {
        int s = c & (STAGES - 1);
        mbar_wait(full0 + s * 8, (c >> 3) & 1);

        unsigned long long xrc = sxu[s * (STAGE_BYTES / 8) + xoff];
        unsigned long long xic = sxu[s * (STAGE_BYTES / 8) + (TL * Mn / 2) + xoff];
        unsigned long long nxi = xic ^ SMSK;

#pragma unroll
        for (int f = 0; f < 8; ++f) {
            ulonglong2 w = swl[f * Cn + c];    // broadcast LDS.128
            ar[f] = ffma2(w.x, xrc, ar[f]);
            ar[f] = ffma2(w.y, nxi, ar[f]);
            ai[f] = ffma2(w.x, xic, ai[f]);
            ai[f] = ffma2(w.y, xrc, ai[f]);
        }

        if (lane == 0) mbar_arrive(empty0 + s * 8);

        if (tid == 0 && c < Cn - STAGES) {
            int kn = c + STAGES;
            // stage s free once all 16 warps arrived for round (c>>3)
            mbar_wait(empty0 + s * 8, (c >> 3) & 1);
            fence_async();
            uint32_t bar = full0 + s * 8;
            uint32_t sdst = sxb + s * STAGE_BYTES;
            mbar_expect_tx(bar, STAGE_BYTES);
            bulk_cp(sdst, gxr + (size_t)kn * cstride, TL * Mn * 4, bar);
            bulk_cp(sdst + TL * Mn * 4, gxi + (size_t)kn * cstride, TL * Mn * 4, bar);
        }
    }

    int l = lt + li;
    float sc = sqrtf(1.0f + (float)l) * (1.0f / 32.0f);
    float* obase = out + ((size_t)b * Fn * Ln + l) * Mn + mt * 2;

#pragma unroll
    for (int f = 0; f < 8; ++f) {
        U64 u;
        u.u = ar[f];
        float2 vr2;
        vr2.x = fmaxf(u.f.x * sc, 0.0f);
        vr2.y = fmaxf(u.f.y * sc, 0.0f);
        *reinterpret_cast<float2*>(obase + (size_t)f * LM) = vr2;

        u.u = ai[f];
        float2 vi2;
        vi2.x = u.f.x * sc;
        vi2.y = u.f.y * sc;
        *reinterpret_cast<float2*>(obase + IMAG_OFF + (size_t)f * LM) = vi2;
    }
}

extern "C" void kernel_launch(void* const* d_in, const int* in_sizes, int n_in,
                              void* d_out, int out_size) {
    const float* x_real = (const float*)d_in[0];
    const float* x_imag = (const float*)d_in[1];
    const float* w_real = (const float*)d_in[2];
    const float* w_imag = (const float*)d_in[3];
    float* out = (float*)d_out;

    static bool attr_set = false;
    if (!attr_set) {
        cudaFuncSetAttribute(sphere_tl_kernel,
                             cudaFuncAttributeMaxDynamicSharedMemorySize,
                             SMEM_TOTAL);
        attr_set = true;
    }

    sphere_tl_kernel<<<Bn * (Ln / TL), THREADS, SMEM_TOTAL>>>(
        x_real, x_imag, w_real, w_imag, out);
}

// round 7
// speedup vs baseline: 1.3908x; 1.3908x over previous
#include <cuda_runtime.h>
#include <cstdint>

// Problem constants
#define Bn 4
#define Cn 32
#define Ln 256
#define Mn 256
#define Fn 8
#define Nn 64
#define FC (Fn * Cn)          // 256
#define LM (Ln * Mn)          // 65536
#define IMAG_OFF ((size_t)Bn * Fn * LM)  // 2,097,152
#define CB 8                  // c-batch size (front-batched loads)

union U64 {
    unsigned long long u;
    float2 f;
};

__device__ __forceinline__ unsigned long long ffma2(unsigned long long a,
                                                    unsigned long long b,
                                                    unsigned long long c) {
    unsigned long long d;
    asm("fma.rn.f32x2 %0, %1, %2, %3;" : "=l"(d) : "l"(a), "l"(b), "l"(c));
    return d;
}

// ---------------------------------------------------------------------------
// Grid: B*L = 1024 blocks, 128 threads. Block = one (b, l).
// Thread t: m-pair t (2 consecutive m), all 8 f.
// c-loop in 4 batches of 8: 16 front-batched LDG.64 (MLP_eff ~16), then
// 8 c x 8 f x 4 ffma2. Weights broadcast from shared (LDS.128).
// ---------------------------------------------------------------------------
__global__ __launch_bounds__(128, 6) void sphere_v7_kernel(
    const float* __restrict__ xr,
    const float* __restrict__ xi,
    const float* __restrict__ wr,
    const float* __restrict__ wi,
    float* __restrict__ out) {
    __shared__ ulonglong2 s2[FC];   // 4 KB: { {wr,wr}, {wi,wi} } per (f,c)

    int bid = blockIdx.x;
    int b = bid >> 8;
    int l = bid & (Ln - 1);
    int tid = threadIdx.x;

    // --- interpolate this l's weights into shared ---
    {
        float t = (float)l * (63.0f / 255.0f);
        int lo = (int)t;
        if (lo > Nn - 2) lo = Nn - 2;
        float fr = t - (float)lo;
        float om = 1.0f - fr;
#pragma unroll
        for (int j = 0; j < 2; ++j) {
            int k = tid + j * 128;
            const float* pwr = wr + k * Nn + lo;
            const float* pwi = wi + k * Nn + lo;
            float vr = pwr[0] * om + pwr[1] * fr;
            float vi = pwi[0] * om + pwi[1] * fr;
            U64 ur, ui;
            ur.f = make_float2(vr, vr);
            ui.f = make_float2(vi, vi);
            s2[k] = make_ulonglong2(ur.u, ui.u);
        }
    }
    __syncthreads();

    int m0 = tid * 2;
    const unsigned long long* pr = reinterpret_cast<const unsigned long long*>(
        xr + (size_t)b * Cn * LM + (size_t)l * Mn + m0);
    const unsigned long long* pi = reinterpret_cast<const unsigned long long*>(
        xi + (size_t)b * Cn * LM + (size_t)l * Mn + m0);
    // u64 stride per c
    const int step = LM / 2;   // 32768 u64 -> byte offset 262144, fits imm24

    unsigned long long ar[Fn], ai[Fn];
#pragma unroll
    for (int f = 0; f < Fn; ++f) { ar[f] = 0ull; ai[f] = 0ull; }

    const unsigned long long SMSK = 0x8000000080000000ULL;

#pragma unroll
    for (int cb = 0; cb < Cn; cb += CB) {
        // ---- front-batched loads: 16 LDG.64 with constant offsets ----
        unsigned long long xrv[CB], xiv[CB];
#pragma unroll
        for (int j = 0; j < CB; ++j) {
            xrv[j] = __ldg(pr + j * step);
            xiv[j] = __ldg(pi + j * step);
        }
        pr += CB * step;
        pi += CB * step;

        // ---- compute over the batch ----
#pragma unroll
        for (int j = 0; j < CB; ++j) {
            int c = cb + j;
            unsigned long long xrc = xrv[j];
            unsigned long long xic = xiv[j];
            unsigned long long nxi = xic ^ SMSK;
#pragma unroll
            for (int f = 0; f < Fn; ++f) {
                ulonglong2 w = s2[f * Cn + c];   // broadcast LDS.128
                ar[f] = ffma2(w.x, xrc, ar[f]);
                ar[f] = ffma2(w.y, nxi, ar[f]);
                ai[f] = ffma2(w.x, xic, ai[f]);
                ai[f] = ffma2(w.y, xrc, ai[f]);
            }
        }
    }

    float sc = sqrtf(1.0f + (float)l) * (1.0f / 32.0f);
    float* o_real = out + (size_t)b * Fn * LM + (size_t)l * Mn + m0;
    float* o_imag = o_real + IMAG_OFF;

#pragma unroll
    for (int f = 0; f < Fn; ++f) {
        U64 u;
        u.u = ar[f];
        float2 vr2;
        vr2.x = fmaxf(u.f.x * sc, 0.0f);
        vr2.y = fmaxf(u.f.y * sc, 0.0f);
        *reinterpret_cast<float2*>(o_real + (size_t)f * LM) = vr2;

        u.u = ai[f];
        float2 vi2;
        vi2.x = u.f.x * sc;
        vi2.y = u.f.y * sc;
        *reinterpret_cast<float2*>(o_imag + (size_t)f * LM) = vi2;
    }
}

extern "C" void kernel_launch(void* const* d_in, const int* in_sizes, int n_in,
                              void* d_out, int out_size) {
    const float* x_real = (const float*)d_in[0];
    const float* x_imag = (const float*)d_in[1];
    const float* w_real = (const float*)d_in[2];
    const float* w_imag = (const float*)d_in[3];
    float* out = (float*)d_out;

    sphere_v7_kernel<<<Bn * Ln, 128>>>(x_real, x_imag, w_real, w_imag, out);
}